// round 5
// baseline (speedup 1.0000x reference)
#include <cuda_runtime.h>
#include <math.h>

#define SEQ 32768
#define HID 1024
#define ROWS_PER_BLOCK 8

// Scratch (no device allocation allowed)
__device__ float  g_energies[SEQ];
__device__ double g_sum;

// ---------------------------------------------------------------------------
// Kernel 0: zero the accumulator (must be re-done every call: deterministic)
// ---------------------------------------------------------------------------
__global__ void init_kernel() { g_sum = 0.0; }

// ---------------------------------------------------------------------------
// Kernel 1: energies[row] = dot(enc[row,:], hidden); block also accumulates
// sum(exp(energy)) in double into g_sum (softmax is shift-invariant, and
// double exp cannot overflow for |e| < 700).
// ---------------------------------------------------------------------------
__global__ __launch_bounds__(256) void matvec_kernel(
    const float* __restrict__ hidden,
    const float* __restrict__ enc)
{
    __shared__ float4 sh_h[HID / 4];         // 4 KB
    __shared__ float  sh_e[ROWS_PER_BLOCK];  // per-warp energies

    int tid = threadIdx.x;
    sh_h[tid] = reinterpret_cast<const float4*>(hidden)[tid];
    __syncthreads();

    int warp = tid >> 5;
    int lane = tid & 31;
    int row  = blockIdx.x * ROWS_PER_BLOCK + warp;

    const float4* e4 = reinterpret_cast<const float4*>(enc)
                     + (size_t)row * (HID / 4);

    float acc = 0.0f;
#pragma unroll
    for (int i = 0; i < 8; i++) {
        float4 a = __ldcs(e4 + i * 32 + lane);   // streaming: read-once data
        float4 h = sh_h[i * 32 + lane];
        acc = fmaf(a.x, h.x, acc);
        acc = fmaf(a.y, h.y, acc);
        acc = fmaf(a.z, h.z, acc);
        acc = fmaf(a.w, h.w, acc);
    }

#pragma unroll
    for (int o = 16; o; o >>= 1)
        acc += __shfl_xor_sync(0xffffffffu, acc, o);

    if (lane == 0) {
        g_energies[row] = acc;
        sh_e[warp] = acc;
    }
    __syncthreads();

    // warp 0, lanes 0..7: one double exp each, reduce, single atomic per block
    if (tid < ROWS_PER_BLOCK) {
        double v = exp((double)sh_e[tid]);
#pragma unroll
        for (int o = ROWS_PER_BLOCK / 2; o; o >>= 1)
            v += __shfl_xor_sync(0xffu, v, o);
        if (tid == 0)
            atomicAdd(&g_sum, v);
    }
}

// ---------------------------------------------------------------------------
// Kernel 2: out[i] = exp(e[i]) / S  — fully parallel, energies are L2-hot
// ---------------------------------------------------------------------------
__global__ __launch_bounds__(512) void normalize_kernel(float* __restrict__ out)
{
    int i = blockIdx.x * blockDim.x + threadIdx.x;
    double inv = 1.0 / g_sum;
    out[i] = (float)(exp((double)g_energies[i]) * inv);
}

// ---------------------------------------------------------------------------
extern "C" void kernel_launch(void* const* d_in, const int* in_sizes, int n_in,
                              void* d_out, int out_size)
{
    const float* hidden = (const float*)d_in[0];   // [1024]
    const float* enc    = (const float*)d_in[1];   // [32768, 1024]
    float* out          = (float*)d_out;           // [1,1,32768]

    init_kernel<<<1, 1>>>();
    matvec_kernel<<<SEQ / ROWS_PER_BLOCK, 256>>>(hidden, enc);
    normalize_kernel<<<SEQ / 512, 512>>>(out);
}